// round 16
// baseline (speedup 1.0000x reference)
#include <cuda_runtime.h>
#include <cuda_fp16.h>
#include <cstdint>
#include <cstddef>

#define NN   16384   // nodes
#define F_IN 512     // input feature dim
#define H    256     // hidden dim
#define MAXE 524288  // edges
#define KP2  512     // 2*H   (fp16x2 expanded K, small GEMMs)
#define KPX2 1024    // 2*F_IN

// ---------------- device scratch (no allocations allowed) ----------------
__device__ __half g_supp16[(size_t)NN * H];   // support in fp16 (gather input)
__device__ int   g_cnt[NN];
__device__ int   g_rowptr[NN + 1];
__device__ int   g_cursor[NN];
__device__ int   g_ccol[MAXE];
__device__ float g_cw[MAXE];
__device__ __half g_xs[(size_t)NN * KPX2];    // x split (A-pattern [hi|lo])
__device__ __half g_gcWs[(size_t)H * KPX2];   // gc_W split+transposed (B-pattern [hi|hi])
__device__ __half g_H1s[(size_t)NN * KP2];    // H1 split (A-pattern), written by gather
__device__ __half g_pWs[(size_t)(2 * H) * KP2]; // [node_W | neigh_W] splits (B-pattern)
__device__ __half g_Ah[(size_t)NN * H];       // node_emb fp16 (adj GEMM A)
__device__ __half g_Bh[(size_t)NN * H];       // neigh_emb fp16 (adj GEMM B)

// ---------------- PTX helpers ----------------
__device__ __forceinline__ uint32_t smem_u32(const void* p) {
    uint32_t a;
    asm("{ .reg .u64 t; cvta.to.shared.u64 t, %1; cvt.u32.u64 %0, t; }" : "=r"(a) : "l"(p));
    return a;
}
#define CP_ASYNC16(sm, gp) asm volatile("cp.async.cg.shared.global [%0], [%1], 16;" :: "r"(sm), "l"(gp))
#define CP_COMMIT()        asm volatile("cp.async.commit_group;" ::: "memory")
#define CP_WAIT1()         asm volatile("cp.async.wait_group 1;" ::: "memory")
#define CP_WAIT0()         asm volatile("cp.async.wait_group 0;" ::: "memory")

__device__ __forceinline__ uint32_t sw128(uint32_t off) {
    return off ^ ((off >> 3) & 0x70);
}
__device__ __forceinline__ void ldsm_x4(uint32_t& r0, uint32_t& r1, uint32_t& r2, uint32_t& r3,
                                        uint32_t addr) {
    asm volatile("ldmatrix.sync.aligned.m8n8.x4.shared.b16 {%0,%1,%2,%3}, [%4];"
                 : "=r"(r0), "=r"(r1), "=r"(r2), "=r"(r3) : "r"(addr));
}
__device__ __forceinline__ void mma_f16(float& c0, float& c1, float& c2, float& c3,
                                        uint32_t a0, uint32_t a1, uint32_t a2, uint32_t a3,
                                        uint32_t b0, uint32_t b1) {
    asm volatile("mma.sync.aligned.m16n8k16.row.col.f32.f16.f16.f32 "
                 "{%0,%1,%2,%3}, {%4,%5,%6,%7}, {%8,%9}, {%0,%1,%2,%3};"
                 : "+f"(c0), "+f"(c1), "+f"(c2), "+f"(c3)
                 : "r"(a0), "r"(a1), "r"(a2), "r"(a3), "r"(b0), "r"(b1));
}

// ---------------- small utility kernels ----------------
__global__ void zero_int_kernel(int* p, int n) {
    int i = blockIdx.x * blockDim.x + threadIdx.x;
    if (i < n) p[i] = 0;
}
__global__ void count_edges_kernel(const int* __restrict__ erow, int E, int* __restrict__ cnt) {
    int e = blockIdx.x * blockDim.x + threadIdx.x;
    if (e < E) atomicAdd(&cnt[erow[e]], 1);
}
// exclusive scan of 16384 ints: 1024 threads, 16/thread, shfl-based
__global__ void scan_kernel(const int* __restrict__ cnt, int* __restrict__ rowptr,
                            int* __restrict__ cursor) {
    __shared__ int wsum[32];
    int t = threadIdx.x;
    int lane = t & 31, w = t >> 5;
    int sum = 0;
#pragma unroll
    for (int i = 0; i < 16; i++) sum += cnt[t * 16 + i];
    int s = sum;
#pragma unroll
    for (int off = 1; off < 32; off <<= 1) {
        int n = __shfl_up_sync(0xFFFFFFFFu, s, off);
        if (lane >= off) s += n;
    }
    if (lane == 31) wsum[w] = s;
    __syncthreads();
    if (w == 0) {
        int v = wsum[lane];
#pragma unroll
        for (int off = 1; off < 32; off <<= 1) {
            int n = __shfl_up_sync(0xFFFFFFFFu, v, off);
            if (lane >= off) v += n;
        }
        wsum[lane] = v;
    }
    __syncthreads();
    int base = (w ? wsum[w - 1] : 0) + s - sum;
    int run = base;
#pragma unroll
    for (int i = 0; i < 16; i++) {
        int c = cnt[t * 16 + i];
        rowptr[t * 16 + i] = run;
        cursor[t * 16 + i] = run;
        run += c;
    }
    if (t == 1023) rowptr[NN] = run;
}
__global__ void fill_csr_kernel(const int* __restrict__ erow, const int* __restrict__ ecol,
                                const float* __restrict__ ew, int E,
                                int* __restrict__ cursor, int* __restrict__ ccol,
                                float* __restrict__ cw) {
    int e = blockIdx.x * blockDim.x + threadIdx.x;
    if (e < E) {
        int r = erow[e];
        int p = atomicAdd(&cursor[r], 1);
        ccol[p] = ecol[e];
        cw[p]   = ew[e];
    }
}

// gather + relu + fp16x2 split, fused; fp16 support; edge loop unrolled x4 for MLP.
__global__ __launch_bounds__(256) void gather_relu_h1s_kernel(
    const __half* __restrict__ supp16, const int* __restrict__ ccol,
    const float* __restrict__ cw, const int* __restrict__ rowptr,
    __half* __restrict__ H1s) {
    int r  = blockIdx.x * 4 + (threadIdx.x >> 6);
    int t4 = (threadIdx.x & 63) << 2;
    int beg = rowptr[r], end = rowptr[r + 1];
    float4 acc = make_float4(0.f, 0.f, 0.f, 0.f);
    int j = beg;
    for (; j + 3 < end; j += 4) {
        int   c0 = ccol[j],   c1 = ccol[j + 1], c2 = ccol[j + 2], c3 = ccol[j + 3];
        float w0 = cw[j],     w1 = cw[j + 1],   w2 = cw[j + 2],   w3 = cw[j + 3];
        uint2 r0 = *(const uint2*)(supp16 + (size_t)c0 * H + t4);
        uint2 r1 = *(const uint2*)(supp16 + (size_t)c1 * H + t4);
        uint2 r2 = *(const uint2*)(supp16 + (size_t)c2 * H + t4);
        uint2 r3 = *(const uint2*)(supp16 + (size_t)c3 * H + t4);
        float2 a0 = __half22float2(*(__half2*)&r0.x), b0 = __half22float2(*(__half2*)&r0.y);
        float2 a1 = __half22float2(*(__half2*)&r1.x), b1 = __half22float2(*(__half2*)&r1.y);
        float2 a2 = __half22float2(*(__half2*)&r2.x), b2 = __half22float2(*(__half2*)&r2.y);
        float2 a3 = __half22float2(*(__half2*)&r3.x), b3 = __half22float2(*(__half2*)&r3.y);
        acc.x += w0 * a0.x + w1 * a1.x + w2 * a2.x + w3 * a3.x;
        acc.y += w0 * a0.y + w1 * a1.y + w2 * a2.y + w3 * a3.y;
        acc.z += w0 * b0.x + w1 * b1.x + w2 * b2.x + w3 * b3.x;
        acc.w += w0 * b0.y + w1 * b1.y + w2 * b2.y + w3 * b3.y;
    }
    for (; j < end; j++) {
        int c0 = ccol[j]; float w0 = cw[j];
        uint2 raw = *(const uint2*)(supp16 + (size_t)c0 * H + t4);
        float2 f01 = __half22float2(*(__half2*)&raw.x);
        float2 f23 = __half22float2(*(__half2*)&raw.y);
        acc.x += w0 * f01.x; acc.y += w0 * f01.y;
        acc.z += w0 * f23.x; acc.w += w0 * f23.y;
    }
    float v[4] = {fmaxf(acc.x, 0.f), fmaxf(acc.y, 0.f), fmaxf(acc.z, 0.f), fmaxf(acc.w, 0.f)};
    __half hi[4], lo[4];
#pragma unroll
    for (int i = 0; i < 4; i++) {
        hi[i] = __float2half_rn(v[i]);
        lo[i] = __float2half_rn(v[i] - __half2float(hi[i]));
    }
    size_t base = (size_t)r * KP2;
    *(uint2*)&H1s[base + t4]       = *(uint2*)hi;
    *(uint2*)&H1s[base + 256 + t4] = *(uint2*)lo;
}

// fp32 -> fp16x2 split. bpat=0: A-pattern [hi|lo]; bpat=1: B-pattern [hi|hi]
__global__ void split2_kernel(const float* __restrict__ src, __half* __restrict__ dst,
                              int K, int bpat, int total) {
    int idx = blockIdx.x * blockDim.x + threadIdx.x;
    if (idx >= total) return;
    int r = idx / K, k = idx - r * K;
    size_t base = (size_t)r * (2 * K);
    float v = src[idx];
    __half vh = __float2half_rn(v);
    __half vl = __float2half_rn(v - __half2float(vh));
    dst[base + k]     = vh;
    dst[base + K + k] = bpat ? vh : vl;
}

// W[K,N] row-major -> dst[N, 2K] B-pattern [hi|hi] (transpose + split), for x @ gc_W
__global__ void split2T_kernel(const float* __restrict__ W, __half* __restrict__ dst,
                               int K, int N, int total) {
    int idx = blockIdx.x * blockDim.x + threadIdx.x;
    if (idx >= total) return;
    int k = idx / N, n = idx - k * N;
    size_t base = (size_t)n * (2 * K);
    __half vh = __float2half_rn(W[idx]);
    dst[base + k]     = vh;
    dst[base + K + k] = vh;
}

// ---------------- unified HMMA fp16 GEMM ----------------
// CTA tile 128 x (NF*32); warp tile 64 x (NF*8), 8 warps (2M x 4N).
// NF=4: 128x128 tile, 96KB smem, occ 2.  NF=8: 128x256 tile, 144KB smem, occ 1.
// DIRECT: register-direct epilogue. DUAL: blockIdx.x>=2 -> second output set.
template <int NF>
__device__ __forceinline__ void load_stage_t(const char* __restrict__ Ab,
                                             const char* __restrict__ Bb,
                                             uint32_t stA, uint32_t stB,
                                             int bm0, int bn0, int kt, int Kp, int tid) {
    int s  = tid & 7;
    int r0 = tid >> 3;
#pragma unroll
    for (int rr = 0; rr < 128; rr += 32) {
        int r = r0 + rr;
        uint32_t soff = sw128((uint32_t)(r * 128 + s * 16));
        size_t gA = ((size_t)(bm0 + r) * Kp + kt * 64) * 2 + s * 16;
        CP_ASYNC16(stA + soff, Ab + gA);
    }
#pragma unroll
    for (int rr = 0; rr < NF * 32; rr += 32) {
        int r = r0 + rr;
        uint32_t soff = sw128((uint32_t)(r * 128 + s * 16));
        size_t gB = ((size_t)(bn0 + r) * Kp + kt * 64) * 2 + s * 16;
        CP_ASYNC16(stB + soff, Bb + gB);
    }
}

template <int NCHUNK, bool DIRECT, bool DUAL, int NF>
__global__ __launch_bounds__(256, (NF == 4 ? 2 : 1))
void hmma_gemm_kernel(const __half* __restrict__ A,
                      const __half* __restrict__ B,
                      const float* __restrict__ bias,
                      const float* __restrict__ biasb,
                      float* __restrict__ C,
                      float* __restrict__ Cb,
                      __half* __restrict__ C16,
                      __half* __restrict__ C16b,
                      int ldc) {
    constexpr uint32_t A_BYTES = 16384u;
    constexpr uint32_t B_BYTES = (uint32_t)NF * 32u * 128u;
    constexpr uint32_t STAGE   = A_BYTES + B_BYTES;
    extern __shared__ char smem[];
    uint32_t sb = smem_u32(smem);
    const int tid = threadIdx.x;
    const int wid = tid >> 5, lid = tid & 31;
    const int warp_m = wid >> 2;
    const int warp_n = wid & 3;
    const int bn0 = blockIdx.x * (NF * 32);
    const int bm0 = blockIdx.y * 128;
    const char* Ab = (const char*)A;
    const char* Bb = (const char*)B;
    const int Kp = NCHUNK * 64;

    float acc[4][NF][4];
#pragma unroll
    for (int i = 0; i < 4; i++)
#pragma unroll
        for (int j = 0; j < NF; j++)
#pragma unroll
            for (int q = 0; q < 4; q++) acc[i][j][q] = 0.f;

    load_stage_t<NF>(Ab, Bb, sb, sb + A_BYTES, bm0, bn0, 0, Kp, tid);
    CP_COMMIT();
    load_stage_t<NF>(Ab, Bb, sb + STAGE, sb + STAGE + A_BYTES, bm0, bn0, 1, Kp, tid);
    CP_COMMIT();

    const int a_row   = (lid & 15);
    const int a_chunk = (lid >> 4);
    const int b_nin   = (lid & 7) + ((lid >> 4) << 3);
    const int b_chunk = (lid >> 3) & 1;

#pragma unroll
    for (int i = 0; i < NCHUNK; i++) {
        if (i < NCHUNK - 1) CP_WAIT1(); else CP_WAIT0();
        __syncthreads();
        uint32_t stA = sb + (uint32_t)(i % 3) * STAGE;
        uint32_t stB = stA + A_BYTES;

#pragma unroll
        for (int kk = 0; kk < 4; kk++) {
            uint32_t af[4][4];
#pragma unroll
            for (int im = 0; im < 4; im++) {
                uint32_t off = (uint32_t)((warp_m * 64 + im * 16 + a_row) * 128
                                          + kk * 32 + a_chunk * 16);
                ldsm_x4(af[im][0], af[im][1], af[im][2], af[im][3], stA + sw128(off));
            }
            uint32_t bf[NF][2];
#pragma unroll
            for (int bt = 0; bt < NF / 2; bt++) {
                uint32_t off = (uint32_t)((warp_n * (NF * 8) + bt * 16 + b_nin) * 128
                                          + kk * 32 + b_chunk * 16);
                uint32_t r0, r1, r2, r3;
                ldsm_x4(r0, r1, r2, r3, stB + sw128(off));
                bf[bt * 2 + 0][0] = r0; bf[bt * 2 + 0][1] = r1;
                bf[bt * 2 + 1][0] = r2; bf[bt * 2 + 1][1] = r3;
            }
#pragma unroll
            for (int im = 0; im < 4; im++)
#pragma unroll
                for (int in = 0; in < NF; in++)
                    mma_f16(acc[im][in][0], acc[im][in][1], acc[im][in][2], acc[im][in][3],
                            af[im][0], af[im][1], af[im][2], af[im][3],
                            bf[in][0], bf[in][1]);
        }

        if (i + 2 < NCHUNK) {
            uint32_t nstA = sb + (uint32_t)((i + 2) % 3) * STAGE;
            load_stage_t<NF>(Ab, Bb, nstA, nstA + A_BYTES, bm0, bn0, i + 2, Kp, tid);
            CP_COMMIT();
        }
    }

    if (DIRECT) {
        const int qrow = lid >> 2;
        const int qcol = (lid & 3) * 2;
#pragma unroll
        for (int im = 0; im < 4; im++) {
            size_t row0 = (size_t)(bm0 + warp_m * 64 + im * 16 + qrow);
#pragma unroll
            for (int in = 0; in < NF; in++) {
                int col = bn0 + warp_n * (NF * 8) + in * 8 + qcol;
                *(float2*)(C + row0 * ldc + col)       = make_float2(acc[im][in][0], acc[im][in][1]);
                *(float2*)(C + (row0 + 8) * ldc + col) = make_float2(acc[im][in][2], acc[im][in][3]);
            }
        }
        return;
    }

    // smem-staged epilogue (bias + optional fp32/fp16 outputs; DUAL output select)
    __syncthreads();
    float* Cs = (float*)smem;           // [128][132] (NF==4 path only)
    const int qrow = lid >> 2;
    const int qcol = (lid & 3) * 2;
#pragma unroll
    for (int im = 0; im < 4; im++) {
#pragma unroll
        for (int in = 0; in < NF; in++) {
            int row = warp_m * 64 + im * 16 + qrow;
            int col = warp_n * (NF * 8) + in * 8 + qcol;
            *(float2*)&Cs[row * 132 + col]        = make_float2(acc[im][in][0], acc[im][in][1]);
            *(float2*)&Cs[(row + 8) * 132 + col]  = make_float2(acc[im][in][2], acc[im][in][3]);
        }
    }
    __syncthreads();
    {
        float* Cuse = C; const float* bias_use = bias; __half* C16use = C16;
        int bnc = bn0;
        if (DUAL && blockIdx.x >= 2) {
            Cuse = Cb; bias_use = biasb; C16use = C16b; bnc = bn0 - 256;
        }
        int row = tid >> 1;
        int c0  = (tid & 1) * 64;
        const float* src = &Cs[row * 132 + c0];
        float* dst = Cuse ? (Cuse + (size_t)(bm0 + row) * ldc + bnc + c0) : nullptr;
        __half* dst16 = C16use ? (C16use + (size_t)(bm0 + row) * 256 + bnc + c0) : nullptr;
#pragma unroll
        for (int j = 0; j < 16; j++) {
            float4 v = *(const float4*)(src + j * 4);
            if (bias_use) {
                float4 bv = *(const float4*)(bias_use + bnc + c0 + j * 4);
                v.x += bv.x; v.y += bv.y; v.z += bv.z; v.w += bv.w;
            }
            if (dst) *(float4*)(dst + j * 4) = v;
            if (dst16) {
                __half2 h0 = __floats2half2_rn(v.x, v.y);
                __half2 h1 = __floats2half2_rn(v.z, v.w);
                uint2 pk; pk.x = *(uint32_t*)&h0; pk.y = *(uint32_t*)&h1;
                *(uint2*)(dst16 + j * 4) = pk;
            }
        }
    }
}

#define SMEM_NF4 (3 * (16384 + 16384))   // 96KB
#define SMEM_NF8 (3 * (16384 + 32768))   // 144KB

// ---------------- launch ----------------
extern "C" void kernel_launch(void* const* d_in, const int* in_sizes, int n_in,
                              void* d_out, int out_size) {
    const float* x      = (const float*)d_in[0];
    const int*   erow   = (const int*)d_in[1];
    const int*   ecol   = (const int*)d_in[2];
    const float* ew     = (const float*)d_in[3];
    const float* gcW    = (const float*)d_in[4];
    const float* nodeW  = (const float*)d_in[5];
    const float* nodeb  = (const float*)d_in[6];
    const float* neighW = (const float*)d_in[7];
    const float* neighb = (const float*)d_in[8];

    float* out       = (float*)d_out;
    float* adj       = out;
    float* node_emb  = out + (size_t)NN * NN;
    float* neigh_emb = node_emb + (size_t)NN * H;

    const int E = in_sizes[1];

    float *cw;
    int *cnt, *rowptr, *cursor, *ccol;
    __half *supp16, *xs, *gcWs, *H1s, *pWs, *A2, *B2;
    cudaGetSymbolAddress((void**)&supp16,  g_supp16);
    cudaGetSymbolAddress((void**)&cnt,     g_cnt);
    cudaGetSymbolAddress((void**)&rowptr,  g_rowptr);
    cudaGetSymbolAddress((void**)&cursor,  g_cursor);
    cudaGetSymbolAddress((void**)&ccol,    g_ccol);
    cudaGetSymbolAddress((void**)&cw,      g_cw);
    cudaGetSymbolAddress((void**)&xs,      g_xs);
    cudaGetSymbolAddress((void**)&gcWs,    g_gcWs);
    cudaGetSymbolAddress((void**)&H1s,     g_H1s);
    cudaGetSymbolAddress((void**)&pWs,     g_pWs);
    cudaGetSymbolAddress((void**)&A2,      g_Ah);
    cudaGetSymbolAddress((void**)&B2,      g_Bh);

    static cudaStream_t s1 = nullptr;
    static cudaEvent_t evFork = nullptr, evJoin = nullptr;
    static bool init_done = false;
    if (!init_done) {
        cudaFuncSetAttribute((const void*)hmma_gemm_kernel<16, false, false, 4>,
                             cudaFuncAttributeMaxDynamicSharedMemorySize, SMEM_NF4);
        cudaFuncSetAttribute((const void*)hmma_gemm_kernel<8, false, true, 4>,
                             cudaFuncAttributeMaxDynamicSharedMemorySize, SMEM_NF4);
        cudaFuncSetAttribute((const void*)hmma_gemm_kernel<4, true, false, 8>,
                             cudaFuncAttributeMaxDynamicSharedMemorySize, SMEM_NF8);
        cudaStreamCreateWithFlags(&s1, cudaStreamNonBlocking);
        cudaEventCreateWithFlags(&evFork, cudaEventDisableTiming);
        cudaEventCreateWithFlags(&evJoin, cudaEventDisableTiming);
        init_done = true;
    }

    // ---- fork: CSR chain on s1, split+support GEMM on stream 0 ----
    cudaEventRecord(evFork, 0);
    cudaStreamWaitEvent(s1, evFork, 0);

    // branch B (s1): CSR build
    zero_int_kernel<<<(NN + 255) / 256, 256, 0, s1>>>(cnt, NN);
    count_edges_kernel<<<(E + 255) / 256, 256, 0, s1>>>(erow, E, cnt);
    scan_kernel<<<1, 1024, 0, s1>>>(cnt, rowptr, cursor);
    fill_csr_kernel<<<(E + 255) / 256, 256, 0, s1>>>(erow, ecol, ew, E, cursor, ccol, cw);
    cudaEventRecord(evJoin, s1);

    // branch A (stream 0): splits + support GEMM (fp16-only output)
    split2_kernel<<<(NN * F_IN + 255) / 256, 256>>>(x, xs, F_IN, 0, NN * F_IN);
    split2T_kernel<<<(F_IN * H + 255) / 256, 256>>>(gcW, gcWs, F_IN, H, F_IN * H);
    hmma_gemm_kernel<16, false, false, 4><<<dim3(H / 128, NN / 128), 256, SMEM_NF4>>>(
        xs, gcWs, nullptr, nullptr, nullptr, nullptr, supp16, nullptr, H);

    // ---- join ----
    cudaStreamWaitEvent(0, evJoin, 0);

    // gather (needs CSR + supp16) + relu + split
    gather_relu_h1s_kernel<<<NN / 4, 256>>>(supp16, ccol, cw, rowptr, H1s);
    // weight splits into concatenated [node | neigh] array
    split2_kernel<<<(H * H + 255) / 256, 256>>>(nodeW, pWs, H, 1, H * H);
    split2_kernel<<<(H * H + 255) / 256, 256>>>(neighW, pWs + (size_t)H * KP2, H, 1, H * H);
    // merged projections (DUAL): N=512 -> node_emb / neigh_emb + fp16 copies
    hmma_gemm_kernel<8, false, true, 4><<<dim3((2 * H) / 128, NN / 128), 256, SMEM_NF4>>>(
        H1s, pWs, nodeb, neighb, node_emb, neigh_emb, A2, B2, H);
    // adj = node_emb @ neigh_emb^T (plain fp16, Kp=256, 128x256 tile, direct epilogue)
    hmma_gemm_kernel<4, true, false, 8><<<dim3(NN / 256, NN / 128), 256, SMEM_NF8>>>(
        A2, B2, nullptr, nullptr, adj, nullptr, nullptr, nullptr, NN);
}

// round 17
// speedup vs baseline: 1.0422x; 1.0422x over previous
#include <cuda_runtime.h>
#include <cuda_fp16.h>
#include <cstdint>
#include <cstddef>

#define NN   16384   // nodes
#define F_IN 512     // input feature dim
#define H    256     // hidden dim
#define MAXE 524288  // edges
#define KP2  512     // 2*H   (fp16x2 expanded K, small GEMMs)
#define KPX2 1024    // 2*F_IN

// ---------------- device scratch (no allocations allowed) ----------------
__device__ __half g_supp16[(size_t)NN * H];   // support in fp16 (gather input)
__device__ int   g_cnt[NN];
__device__ int   g_rowptr[NN + 1];
__device__ int   g_cursor[NN];
__device__ int   g_ccol[MAXE];
__device__ float g_cw[MAXE];
__device__ __half g_xs[(size_t)NN * KPX2];    // x split (A-pattern [hi|lo])
__device__ __half g_gcWs[(size_t)H * KPX2];   // gc_W split+transposed (B-pattern [hi|hi])
__device__ __half g_H1s[(size_t)NN * KP2];    // H1 split (A-pattern), written by gather
__device__ __half g_pWs[(size_t)(2 * H) * KP2]; // [node_W | neigh_W] splits (B-pattern)
__device__ __half g_Ah[(size_t)NN * H];       // node_emb fp16 (adj GEMM A)
__device__ __half g_Bh[(size_t)NN * H];       // neigh_emb fp16 (adj GEMM B)

// ---------------- PTX helpers ----------------
__device__ __forceinline__ uint32_t smem_u32(const void* p) {
    uint32_t a;
    asm("{ .reg .u64 t; cvta.to.shared.u64 t, %1; cvt.u32.u64 %0, t; }" : "=r"(a) : "l"(p));
    return a;
}
#define CP_ASYNC16(sm, gp) asm volatile("cp.async.cg.shared.global [%0], [%1], 16;" :: "r"(sm), "l"(gp))
#define CP_COMMIT()        asm volatile("cp.async.commit_group;" ::: "memory")
#define CP_WAIT1()         asm volatile("cp.async.wait_group 1;" ::: "memory")
#define CP_WAIT0()         asm volatile("cp.async.wait_group 0;" ::: "memory")

__device__ __forceinline__ uint32_t sw128(uint32_t off) {
    return off ^ ((off >> 3) & 0x70);
}
__device__ __forceinline__ void ldsm_x4(uint32_t& r0, uint32_t& r1, uint32_t& r2, uint32_t& r3,
                                        uint32_t addr) {
    asm volatile("ldmatrix.sync.aligned.m8n8.x4.shared.b16 {%0,%1,%2,%3}, [%4];"
                 : "=r"(r0), "=r"(r1), "=r"(r2), "=r"(r3) : "r"(addr));
}
__device__ __forceinline__ void mma_f16(float& c0, float& c1, float& c2, float& c3,
                                        uint32_t a0, uint32_t a1, uint32_t a2, uint32_t a3,
                                        uint32_t b0, uint32_t b1) {
    asm volatile("mma.sync.aligned.m16n8k16.row.col.f32.f16.f16.f32 "
                 "{%0,%1,%2,%3}, {%4,%5,%6,%7}, {%8,%9}, {%0,%1,%2,%3};"
                 : "+f"(c0), "+f"(c1), "+f"(c2), "+f"(c3)
                 : "r"(a0), "r"(a1), "r"(a2), "r"(a3), "r"(b0), "r"(b1));
}

// ---------------- small utility kernels ----------------
__global__ void zero_int_kernel(int* p, int n) {
    int i = blockIdx.x * blockDim.x + threadIdx.x;
    if (i < n) p[i] = 0;
}
__global__ void count_edges_kernel(const int* __restrict__ erow, int E, int* __restrict__ cnt) {
    int e = blockIdx.x * blockDim.x + threadIdx.x;
    if (e < E) atomicAdd(&cnt[erow[e]], 1);
}
// exclusive scan of 16384 ints: 1024 threads, 16/thread, shfl-based
__global__ void scan_kernel(const int* __restrict__ cnt, int* __restrict__ rowptr,
                            int* __restrict__ cursor) {
    __shared__ int wsum[32];
    int t = threadIdx.x;
    int lane = t & 31, w = t >> 5;
    int sum = 0;
#pragma unroll
    for (int i = 0; i < 16; i++) sum += cnt[t * 16 + i];
    int s = sum;
#pragma unroll
    for (int off = 1; off < 32; off <<= 1) {
        int n = __shfl_up_sync(0xFFFFFFFFu, s, off);
        if (lane >= off) s += n;
    }
    if (lane == 31) wsum[w] = s;
    __syncthreads();
    if (w == 0) {
        int v = wsum[lane];
#pragma unroll
        for (int off = 1; off < 32; off <<= 1) {
            int n = __shfl_up_sync(0xFFFFFFFFu, v, off);
            if (lane >= off) v += n;
        }
        wsum[lane] = v;
    }
    __syncthreads();
    int base = (w ? wsum[w - 1] : 0) + s - sum;
    int run = base;
#pragma unroll
    for (int i = 0; i < 16; i++) {
        int c = cnt[t * 16 + i];
        rowptr[t * 16 + i] = run;
        cursor[t * 16 + i] = run;
        run += c;
    }
    if (t == 1023) rowptr[NN] = run;
}
__global__ void fill_csr_kernel(const int* __restrict__ erow, const int* __restrict__ ecol,
                                const float* __restrict__ ew, int E,
                                int* __restrict__ cursor, int* __restrict__ ccol,
                                float* __restrict__ cw) {
    int e = blockIdx.x * blockDim.x + threadIdx.x;
    if (e < E) {
        int r = erow[e];
        int p = atomicAdd(&cursor[r], 1);
        ccol[p] = ecol[e];
        cw[p]   = ew[e];
    }
}

// gather + relu + fp16x2 split, fused; fp16 support; edge loop unrolled x4 for MLP.
__global__ __launch_bounds__(256) void gather_relu_h1s_kernel(
    const __half* __restrict__ supp16, const int* __restrict__ ccol,
    const float* __restrict__ cw, const int* __restrict__ rowptr,
    __half* __restrict__ H1s) {
    int r  = blockIdx.x * 4 + (threadIdx.x >> 6);
    int t4 = (threadIdx.x & 63) << 2;
    int beg = rowptr[r], end = rowptr[r + 1];
    float4 acc = make_float4(0.f, 0.f, 0.f, 0.f);
    int j = beg;
    for (; j + 3 < end; j += 4) {
        int   c0 = ccol[j],   c1 = ccol[j + 1], c2 = ccol[j + 2], c3 = ccol[j + 3];
        float w0 = cw[j],     w1 = cw[j + 1],   w2 = cw[j + 2],   w3 = cw[j + 3];
        uint2 r0 = *(const uint2*)(supp16 + (size_t)c0 * H + t4);
        uint2 r1 = *(const uint2*)(supp16 + (size_t)c1 * H + t4);
        uint2 r2 = *(const uint2*)(supp16 + (size_t)c2 * H + t4);
        uint2 r3 = *(const uint2*)(supp16 + (size_t)c3 * H + t4);
        float2 a0 = __half22float2(*(__half2*)&r0.x), b0 = __half22float2(*(__half2*)&r0.y);
        float2 a1 = __half22float2(*(__half2*)&r1.x), b1 = __half22float2(*(__half2*)&r1.y);
        float2 a2 = __half22float2(*(__half2*)&r2.x), b2 = __half22float2(*(__half2*)&r2.y);
        float2 a3 = __half22float2(*(__half2*)&r3.x), b3 = __half22float2(*(__half2*)&r3.y);
        acc.x += w0 * a0.x + w1 * a1.x + w2 * a2.x + w3 * a3.x;
        acc.y += w0 * a0.y + w1 * a1.y + w2 * a2.y + w3 * a3.y;
        acc.z += w0 * b0.x + w1 * b1.x + w2 * b2.x + w3 * b3.x;
        acc.w += w0 * b0.y + w1 * b1.y + w2 * b2.y + w3 * b3.y;
    }
    for (; j < end; j++) {
        int c0 = ccol[j]; float w0 = cw[j];
        uint2 raw = *(const uint2*)(supp16 + (size_t)c0 * H + t4);
        float2 f01 = __half22float2(*(__half2*)&raw.x);
        float2 f23 = __half22float2(*(__half2*)&raw.y);
        acc.x += w0 * f01.x; acc.y += w0 * f01.y;
        acc.z += w0 * f23.x; acc.w += w0 * f23.y;
    }
    float v[4] = {fmaxf(acc.x, 0.f), fmaxf(acc.y, 0.f), fmaxf(acc.z, 0.f), fmaxf(acc.w, 0.f)};
    __half hi[4], lo[4];
#pragma unroll
    for (int i = 0; i < 4; i++) {
        hi[i] = __float2half_rn(v[i]);
        lo[i] = __float2half_rn(v[i] - __half2float(hi[i]));
    }
    size_t base = (size_t)r * KP2;
    *(uint2*)&H1s[base + t4]       = *(uint2*)hi;
    *(uint2*)&H1s[base + 256 + t4] = *(uint2*)lo;
}

// fp32 -> fp16x2 split. bpat=0: A-pattern [hi|lo]; bpat=1: B-pattern [hi|hi]
__global__ void split2_kernel(const float* __restrict__ src, __half* __restrict__ dst,
                              int K, int bpat, int total) {
    int idx = blockIdx.x * blockDim.x + threadIdx.x;
    if (idx >= total) return;
    int r = idx / K, k = idx - r * K;
    size_t base = (size_t)r * (2 * K);
    float v = src[idx];
    __half vh = __float2half_rn(v);
    __half vl = __float2half_rn(v - __half2float(vh));
    dst[base + k]     = vh;
    dst[base + K + k] = bpat ? vh : vl;
}

// W[K,N] row-major -> dst[N, 2K] B-pattern [hi|hi] (transpose + split), for x @ gc_W
__global__ void split2T_kernel(const float* __restrict__ W, __half* __restrict__ dst,
                               int K, int N, int total) {
    int idx = blockIdx.x * blockDim.x + threadIdx.x;
    if (idx >= total) return;
    int k = idx / N, n = idx - k * N;
    size_t base = (size_t)n * (2 * K);
    __half vh = __float2half_rn(W[idx]);
    dst[base + k]     = vh;
    dst[base + K + k] = vh;
}

// ---------------- unified HMMA fp16 GEMM (128x128 CTA tile, occ 2) ----------------
// C = A[M, NCHUNK*64] @ B[N, NCHUNK*64]^T (+bias); fp32 out optional; fp16 out optional.
// DIRECT: register-direct epilogue (adj). DUAL: blockIdx.x>=2 -> second output set.
#define STAGE_SZ 32768u       // A 16KB + B 16KB
#define GEMM_SMEM (3 * 32768) // 96KB -> 2 CTAs/SM; epilogue Cs[128][132] aliases

__device__ __forceinline__ void load_stage(const char* __restrict__ Ab,
                                           const char* __restrict__ Bb,
                                           uint32_t stA, uint32_t stB,
                                           int bm0, int bn0, int kt, int Kp, int tid) {
    int s  = tid & 7;
    int r0 = tid >> 3;
#pragma unroll
    for (int rr = 0; rr < 128; rr += 32) {
        int r = r0 + rr;
        uint32_t soff = sw128((uint32_t)(r * 128 + s * 16));
        size_t gA = ((size_t)(bm0 + r) * Kp + kt * 64) * 2 + s * 16;
        size_t gB = ((size_t)(bn0 + r) * Kp + kt * 64) * 2 + s * 16;
        CP_ASYNC16(stA + soff, Ab + gA);
        CP_ASYNC16(stB + soff, Bb + gB);
    }
}

template <int NCHUNK, bool DIRECT, bool DUAL>
__global__ __launch_bounds__(256, 2)
void hmma_gemm_kernel(const __half* __restrict__ A,
                      const __half* __restrict__ B,
                      const float* __restrict__ bias,
                      const float* __restrict__ biasb,
                      float* __restrict__ C,
                      float* __restrict__ Cb,
                      __half* __restrict__ C16,
                      __half* __restrict__ C16b,
                      int ldc) {
    extern __shared__ char smem[];
    uint32_t sb = smem_u32(smem);
    const int tid = threadIdx.x;
    const int wid = tid >> 5, lid = tid & 31;
    const int warp_m = wid >> 2;
    const int warp_n = wid & 3;
    const int bn0 = blockIdx.x * 128;
    const int bm0 = blockIdx.y * 128;
    const char* Ab = (const char*)A;
    const char* Bb = (const char*)B;
    const int Kp = NCHUNK * 64;

    float acc[4][4][4];
#pragma unroll
    for (int i = 0; i < 4; i++)
#pragma unroll
        for (int j = 0; j < 4; j++)
#pragma unroll
            for (int q = 0; q < 4; q++) acc[i][j][q] = 0.f;

    load_stage(Ab, Bb, sb, sb + 16384u, bm0, bn0, 0, Kp, tid);
    CP_COMMIT();
    load_stage(Ab, Bb, sb + STAGE_SZ, sb + STAGE_SZ + 16384u, bm0, bn0, 1, Kp, tid);
    CP_COMMIT();

    const int a_row   = (lid & 15);
    const int a_chunk = (lid >> 4);
    const int b_nin   = (lid & 7) + ((lid >> 4) << 3);
    const int b_chunk = (lid >> 3) & 1;

#pragma unroll
    for (int i = 0; i < NCHUNK; i++) {
        if (i < NCHUNK - 1) CP_WAIT1(); else CP_WAIT0();
        __syncthreads();
        uint32_t stA = sb + (uint32_t)(i % 3) * STAGE_SZ;
        uint32_t stB = stA + 16384u;

#pragma unroll
        for (int kk = 0; kk < 4; kk++) {
            uint32_t af[4][4];
#pragma unroll
            for (int im = 0; im < 4; im++) {
                uint32_t off = (uint32_t)((warp_m * 64 + im * 16 + a_row) * 128
                                          + kk * 32 + a_chunk * 16);
                ldsm_x4(af[im][0], af[im][1], af[im][2], af[im][3], stA + sw128(off));
            }
            uint32_t bf[4][2];
#pragma unroll
            for (int bt = 0; bt < 2; bt++) {
                uint32_t off = (uint32_t)((warp_n * 32 + bt * 16 + b_nin) * 128
                                          + kk * 32 + b_chunk * 16);
                uint32_t r0, r1, r2, r3;
                ldsm_x4(r0, r1, r2, r3, stB + sw128(off));
                bf[bt * 2 + 0][0] = r0; bf[bt * 2 + 0][1] = r1;
                bf[bt * 2 + 1][0] = r2; bf[bt * 2 + 1][1] = r3;
            }
#pragma unroll
            for (int im = 0; im < 4; im++)
#pragma unroll
                for (int in = 0; in < 4; in++)
                    mma_f16(acc[im][in][0], acc[im][in][1], acc[im][in][2], acc[im][in][3],
                            af[im][0], af[im][1], af[im][2], af[im][3],
                            bf[in][0], bf[in][1]);
        }

        if (i + 2 < NCHUNK) {
            uint32_t nstA = sb + (uint32_t)((i + 2) % 3) * STAGE_SZ;
            load_stage(Ab, Bb, nstA, nstA + 16384u, bm0, bn0, i + 2, Kp, tid);
            CP_COMMIT();
        }
    }

    if (DIRECT) {
        const int qrow = lid >> 2;
        const int qcol = (lid & 3) * 2;
#pragma unroll
        for (int im = 0; im < 4; im++) {
            size_t row0 = (size_t)(bm0 + warp_m * 64 + im * 16 + qrow);
#pragma unroll
            for (int in = 0; in < 4; in++) {
                int col = bn0 + warp_n * 32 + in * 8 + qcol;
                *(float2*)(C + row0 * ldc + col)       = make_float2(acc[im][in][0], acc[im][in][1]);
                *(float2*)(C + (row0 + 8) * ldc + col) = make_float2(acc[im][in][2], acc[im][in][3]);
            }
        }
        return;
    }

    __syncthreads();
    float* Cs = (float*)smem;           // [128][132]
    const int qrow = lid >> 2;
    const int qcol = (lid & 3) * 2;
#pragma unroll
    for (int im = 0; im < 4; im++) {
#pragma unroll
        for (int in = 0; in < 4; in++) {
            int row = warp_m * 64 + im * 16 + qrow;
            int col = warp_n * 32 + in * 8 + qcol;
            *(float2*)&Cs[row * 132 + col]        = make_float2(acc[im][in][0], acc[im][in][1]);
            *(float2*)&Cs[(row + 8) * 132 + col]  = make_float2(acc[im][in][2], acc[im][in][3]);
        }
    }
    __syncthreads();
    {
        float* Cuse = C; const float* bias_use = bias; __half* C16use = C16;
        int bnc = bn0;
        if (DUAL && blockIdx.x >= 2) {
            Cuse = Cb; bias_use = biasb; C16use = C16b; bnc = bn0 - 256;
        }
        int row = tid >> 1;
        int c0  = (tid & 1) * 64;
        const float* src = &Cs[row * 132 + c0];
        float* dst = Cuse ? (Cuse + (size_t)(bm0 + row) * ldc + bnc + c0) : nullptr;
        __half* dst16 = C16use ? (C16use + (size_t)(bm0 + row) * 256 + bnc + c0) : nullptr;
#pragma unroll
        for (int j = 0; j < 16; j++) {
            float4 v = *(const float4*)(src + j * 4);
            if (bias_use) {
                float4 bv = *(const float4*)(bias_use + bnc + c0 + j * 4);
                v.x += bv.x; v.y += bv.y; v.z += bv.z; v.w += bv.w;
            }
            if (dst) *(float4*)(dst + j * 4) = v;
            if (dst16) {
                __half2 h0 = __floats2half2_rn(v.x, v.y);
                __half2 h1 = __floats2half2_rn(v.z, v.w);
                uint2 pk; pk.x = *(uint32_t*)&h0; pk.y = *(uint32_t*)&h1;
                *(uint2*)(dst16 + j * 4) = pk;
            }
        }
    }
}

// ---------------- launch ----------------
extern "C" void kernel_launch(void* const* d_in, const int* in_sizes, int n_in,
                              void* d_out, int out_size) {
    const float* x      = (const float*)d_in[0];
    const int*   erow   = (const int*)d_in[1];
    const int*   ecol   = (const int*)d_in[2];
    const float* ew     = (const float*)d_in[3];
    const float* gcW    = (const float*)d_in[4];
    const float* nodeW  = (const float*)d_in[5];
    const float* nodeb  = (const float*)d_in[6];
    const float* neighW = (const float*)d_in[7];
    const float* neighb = (const float*)d_in[8];

    float* out       = (float*)d_out;
    float* adj       = out;
    float* node_emb  = out + (size_t)NN * NN;
    float* neigh_emb = node_emb + (size_t)NN * H;

    const int E = in_sizes[1];

    float *cw;
    int *cnt, *rowptr, *cursor, *ccol;
    __half *supp16, *xs, *gcWs, *H1s, *pWs, *A2, *B2;
    cudaGetSymbolAddress((void**)&supp16,  g_supp16);
    cudaGetSymbolAddress((void**)&cnt,     g_cnt);
    cudaGetSymbolAddress((void**)&rowptr,  g_rowptr);
    cudaGetSymbolAddress((void**)&cursor,  g_cursor);
    cudaGetSymbolAddress((void**)&ccol,    g_ccol);
    cudaGetSymbolAddress((void**)&cw,      g_cw);
    cudaGetSymbolAddress((void**)&xs,      g_xs);
    cudaGetSymbolAddress((void**)&gcWs,    g_gcWs);
    cudaGetSymbolAddress((void**)&H1s,     g_H1s);
    cudaGetSymbolAddress((void**)&pWs,     g_pWs);
    cudaGetSymbolAddress((void**)&A2,      g_Ah);
    cudaGetSymbolAddress((void**)&B2,      g_Bh);

    static cudaStream_t s1 = nullptr;
    static cudaEvent_t evFork = nullptr, evJoin = nullptr;
    static bool init_done = false;
    if (!init_done) {
        cudaFuncSetAttribute((const void*)hmma_gemm_kernel<16, false, false>,
                             cudaFuncAttributeMaxDynamicSharedMemorySize, GEMM_SMEM);
        cudaFuncSetAttribute((const void*)hmma_gemm_kernel<8, false, true>,
                             cudaFuncAttributeMaxDynamicSharedMemorySize, GEMM_SMEM);
        cudaFuncSetAttribute((const void*)hmma_gemm_kernel<4, true, false>,
                             cudaFuncAttributeMaxDynamicSharedMemorySize, GEMM_SMEM);
        cudaStreamCreateWithFlags(&s1, cudaStreamNonBlocking);
        cudaEventCreateWithFlags(&evFork, cudaEventDisableTiming);
        cudaEventCreateWithFlags(&evJoin, cudaEventDisableTiming);
        init_done = true;
    }

    // ---- fork: CSR chain + weight splits on s1; x splits + support GEMM on stream 0 ----
    cudaEventRecord(evFork, 0);
    cudaStreamWaitEvent(s1, evFork, 0);

    // branch B (s1): CSR build + projection weight splits (all independent of branch A)
    zero_int_kernel<<<(NN + 255) / 256, 256, 0, s1>>>(cnt, NN);
    count_edges_kernel<<<(E + 255) / 256, 256, 0, s1>>>(erow, E, cnt);
    scan_kernel<<<1, 1024, 0, s1>>>(cnt, rowptr, cursor);
    fill_csr_kernel<<<(E + 255) / 256, 256, 0, s1>>>(erow, ecol, ew, E, cursor, ccol, cw);
    split2_kernel<<<(H * H + 255) / 256, 256, 0, s1>>>(nodeW, pWs, H, 1, H * H);
    split2_kernel<<<(H * H + 255) / 256, 256, 0, s1>>>(neighW, pWs + (size_t)H * KP2, H, 1, H * H);
    cudaEventRecord(evJoin, s1);

    // branch A (stream 0): x splits + support GEMM (fp16-only output)
    split2_kernel<<<(NN * F_IN + 255) / 256, 256>>>(x, xs, F_IN, 0, NN * F_IN);
    split2T_kernel<<<(F_IN * H + 255) / 256, 256>>>(gcW, gcWs, F_IN, H, F_IN * H);
    hmma_gemm_kernel<16, false, false><<<dim3(H / 128, NN / 128), 256, GEMM_SMEM>>>(
        xs, gcWs, nullptr, nullptr, nullptr, nullptr, supp16, nullptr, H);

    // ---- join ----
    cudaStreamWaitEvent(0, evJoin, 0);

    // gather (needs CSR + supp16) + relu + split
    gather_relu_h1s_kernel<<<NN / 4, 256>>>(supp16, ccol, cw, rowptr, H1s);
    // merged projections (DUAL): N=512 -> node_emb / neigh_emb + fp16 copies
    hmma_gemm_kernel<8, false, true><<<dim3((2 * H) / 128, NN / 128), 256, GEMM_SMEM>>>(
        H1s, pWs, nodeb, neighb, node_emb, neigh_emb, A2, B2, H);
    // adj = node_emb @ neigh_emb^T (plain fp16, Kp=256, 128x128 occ-2, direct epilogue)
    hmma_gemm_kernel<4, true, false><<<dim3(NN / 128, NN / 128), 256, GEMM_SMEM>>>(
        A2, B2, nullptr, nullptr, adj, nullptr, nullptr, nullptr, NN);
}